// round 2
// baseline (speedup 1.0000x reference)
#include <cuda_runtime.h>
#include <cuda_bf16.h>
#include <cstdint>

// PQLinear: out[b, d*8+j] = sum_k s[b,d,k] * vectors[d,k,j] + bias
//   where s[b,d,k] = sum_{i : indexes[i,d]==k} x[b,i]
//
// Shapes: x[32,4096] f32, vectors[1376,256,8] f32, bias[11008] f32,
//         indexes[4096,1376] int32 (JAX x64 disabled), out[32,11008] f32.

#define IN_DIM   4096
#define OUT_DIM  11008
#define NS       1376
#define KS       256
#define DS       8
#define BATCH    32

#define G        4        // subspaces per block (1376 / 4 = 344 blocks)
#define TILE     256      // i-tile
#define NTILES   (IN_DIM / TILE)
#define NTHREADS 256
#define SPAD     257      // s row pad: bank = (b + k) % 32, conflict-free
#define XPAD     33       // xs row pad

#define S_ELEMS   (G * BATCH * SPAD)   // 32896 floats
#define XS_ELEMS  (TILE * XPAD)        // 8448 floats
#define IDX_ELEMS (G * TILE)           // 1024 ints
#define SMEM_FLOATS (S_ELEMS + 2 * XS_ELEMS + 2 * IDX_ELEMS)
#define SMEM_BYTES  (SMEM_FLOATS * 4)  // 207360 bytes

__device__ __forceinline__ void load_tile(const float* __restrict__ x,
                                          const int* __restrict__ indexes,
                                          float* __restrict__ xs,
                                          int* __restrict__ idxs,
                                          int i0, int d0, int t, int nthr)
{
    // Index tile: each worked i pulls 4 consecutive int32 (16B, aligned since
    // d0 % 4 == 0 and row stride 1376*4 = 5504 is a multiple of 16).
    for (int ti = t; ti < TILE; ti += nthr) {
        int4 a = *(const int4*)(indexes + (size_t)(i0 + ti) * NS + d0);
        idxs[0 * TILE + ti] = a.x;
        idxs[1 * TILE + ti] = a.y;
        idxs[2 * TILE + ti] = a.z;
        idxs[3 * TILE + ti] = a.w;
    }
    // x tile, transposed into xs[ti][b]. Coalesced float4 reads per batch row.
    const int u_cnt = nthr >> 5;          // threads per batch row (8 or 4)
    const int b = t / u_cnt;
    const int u = t % u_cnt;
    const float4* xp = (const float4*)(x + (size_t)b * IN_DIM + i0);
    for (int r = u; r < TILE / 4; r += u_cnt) {
        float4 v = xp[r];
        int ti = r * 4;
        xs[(ti + 0) * XPAD + b] = v.x;
        xs[(ti + 1) * XPAD + b] = v.y;
        xs[(ti + 2) * XPAD + b] = v.z;
        xs[(ti + 3) * XPAD + b] = v.w;
    }
}

__global__ __launch_bounds__(NTHREADS, 1)
void pq_lut_kernel(const float* __restrict__ x,
                   const float* __restrict__ vectors,
                   const float* __restrict__ bias,
                   const int* __restrict__ indexes,
                   float* __restrict__ out)
{
    extern __shared__ float smem[];
    float* s = smem;                               // [G][BATCH][SPAD]
    float* xs0 = smem + S_ELEMS;                   // [TILE][XPAD] buf 0
    float* xs1 = xs0 + XS_ELEMS;                   // buf 1
    int*   id0 = (int*)(xs1 + XS_ELEMS);           // [G][TILE] buf 0
    int*   id1 = id0 + IDX_ELEMS;                  // buf 1

    const int t    = threadIdx.x;
    const int d0   = blockIdx.x * G;
    const int wid  = t >> 5;
    const int lane = t & 31;

    // Zero histogram accumulators.
    for (int i = t; i < S_ELEMS; i += NTHREADS) s[i] = 0.0f;

    // Prime tile 0 (all threads participate).
    load_tile(x, indexes, xs0, id0, 0, d0, t, NTHREADS);
    __syncthreads();

    // Each histogram warp owns one subspace; lane = batch. Exclusive rows ->
    // no atomics, no cross-warp hazards. Same-address LDS/STS ordering within
    // a thread is HW-guaranteed.
    float* srow = s + wid * (BATCH * SPAD) + lane * SPAD;

    for (int tile = 0; tile < NTILES; tile++) {
        const float* xs  = (tile & 1) ? xs1 : xs0;
        const int*   idc = (tile & 1) ? id1 : id0;
        if (wid < G) {
            const int4* kp = (const int4*)(idc + wid * TILE);
            #pragma unroll 4
            for (int q = 0; q < TILE / 4; q++) {
                int4 k4 = kp[q];
                const float* xr = xs + (q * 4) * XPAD + lane;
                float v0 = xr[0 * XPAD];
                float v1 = xr[1 * XPAD];
                float v2 = xr[2 * XPAD];
                float v3 = xr[3 * XPAD];
                srow[k4.x] += v0;
                srow[k4.y] += v1;
                srow[k4.z] += v2;
                srow[k4.w] += v3;
            }
        } else if (tile + 1 < NTILES) {
            // Warps G..7 prefetch the next tile into the other buffer.
            float* nxs = (tile & 1) ? xs0 : xs1;
            int*   nid = (tile & 1) ? id0 : id1;
            load_tile(x, indexes, nxs, nid, (tile + 1) * TILE, d0,
                      t - G * 32, NTHREADS - G * 32);
        }
        __syncthreads();
    }

    // Phase 2: out[b, (d0+g)*8+j] = sum_k s[g][b][k] * v[g][k][j] + bias.
    // Stage the 4 codebooks (4*256*8 floats = 32KB) into the xs region.
    float* vsh = xs0;  // 8192 floats needed, 8448 available in buf 0
    for (int i = t; i < G * KS * DS; i += NTHREADS)
        vsh[i] = vectors[(size_t)d0 * KS * DS + i];
    __syncthreads();

    {
        const int b = t >> 3;     // 32 batches
        const int j = t & 7;      // 8 output dims per subspace
        #pragma unroll
        for (int g = 0; g < G; g++) {
            const float* sg = s + g * (BATCH * SPAD) + b * SPAD;
            const float* vg = vsh + g * (KS * DS) + j;
            float acc = 0.0f;
            #pragma unroll 8
            for (int k = 0; k < KS; k++)
                acc = fmaf(sg[k], vg[k * DS], acc);
            const int n = (d0 + g) * DS + j;
            out[(size_t)b * OUT_DIM + n] = acc + bias[n];
        }
    }
}

extern "C" void kernel_launch(void* const* d_in, const int* in_sizes, int n_in,
                              void* d_out, int out_size)
{
    const float* x       = (const float*)d_in[0];
    const float* vectors = (const float*)d_in[1];
    const float* bias    = (const float*)d_in[2];
    const int*   indexes = (const int*)d_in[3];
    float*       out     = (float*)d_out;

    cudaFuncSetAttribute(pq_lut_kernel,
                         cudaFuncAttributeMaxDynamicSharedMemorySize,
                         SMEM_BYTES);
    pq_lut_kernel<<<NS / G, NTHREADS, SMEM_BYTES>>>(x, vectors, bias, indexes, out);
}